// round 15
// baseline (speedup 1.0000x reference)
#include <cuda_runtime.h>
#include <math_constants.h>

// Problem constants (fixed by the reference)
#define BB 2
#define TT 512
#define EE 1024
#define SS 2048
#define AA 30

#define GSZ 4
#define NB2 (TT * 4)          // quantized sort key: t0*4 + (w-1)/8
#define NGROUPS_MAX 896       // sum ceil(n_t/4) <= (2048 + 3*512)/4

__device__ float g_scores[BB * TT];
__device__ float g_probs[BB * SS * 32];
__device__ int   g_sorted[SS];
__device__ int4  g_groups[NGROUPS_MAX];   // packed: s0|s1<<16, s2|s3<<16, t0|wmax<<16, cnt
__device__ int   g_ngroups;

// ---------------------------------------------------------------------------
// Kernel 1: scores[b,t] = relu(dot(x[b,t,:], W) + bias). Warp per row, ILP=8.
// ---------------------------------------------------------------------------
__global__ __launch_bounds__(256)
void score_kernel(const float* __restrict__ x,
                  const float* __restrict__ W,
                  const float* __restrict__ bias) {
    const int row  = blockIdx.x * 8 + (threadIdx.x >> 5);   // B*T = 1024 rows
    const int lane = threadIdx.x & 31;

    const float4* __restrict__ xr = reinterpret_cast<const float4*>(x) + (size_t)row * 256;
    const float4* __restrict__ w4 = reinterpret_cast<const float4*>(W);

    float acc = 0.0f;
#pragma unroll
    for (int i = 0; i < 8; ++i) {
        const float4 xv = xr[lane + i * 32];
        const float4 wv = w4[lane + i * 32];
        acc += xv.x * wv.x + xv.y * wv.y + xv.z * wv.z + xv.w * wv.w;
    }
#pragma unroll
    for (int off = 16; off; off >>= 1)
        acc += __shfl_xor_sync(0xffffffffu, acc, off);

    if (lane == 0)
        g_scores[row] = fmaxf(acc + bias[0], 0.0f);
}

// ---------------------------------------------------------------------------
// Kernel 2: softmax probs per (b,s) -> g_probs[b][s][lane], 0 for lane >= w.
// ---------------------------------------------------------------------------
__global__ __launch_bounds__(256)
void prob_kernel(const int* __restrict__ start,
                 const int* __restrict__ end) {
    const int wid  = blockIdx.x * 8 + (threadIdx.x >> 5);   // 0 .. B*S-1
    const int lane = threadIdx.x & 31;
    const int s = wid & (SS - 1);
    const int b = wid >> 11;

    const int t0 = start[s];
    const int w  = end[s] - t0 + 1;                          // 1..30

    float sc = (lane < w) ? g_scores[b * TT + t0 + lane] : -CUDART_INF_F;
    float m = sc;
#pragma unroll
    for (int off = 16; off; off >>= 1)
        m = fmaxf(m, __shfl_xor_sync(0xffffffffu, m, off));
    float e = (lane < w) ? __expf(sc - m) : 0.0f;
    float sum = e;
#pragma unroll
    for (int off = 16; off; off >>= 1)
        sum += __shfl_xor_sync(0xffffffffu, sum, off);

    g_probs[((size_t)b * SS + s) * 32 + lane] = e / sum;     // exactly 0 past w
}

// ---------------------------------------------------------------------------
// Kernel 3: counting sort by quantized key (t0, w-tier) + PACKED descriptors.
// Single block, 1024 threads. Each group descriptor is one int4:
//   x = s0 | s1<<16, y = s2 | s3<<16, z = t0 | wmax<<16, w = cnt
// (duplicate last member for cnt<4; probs are zero-padded so dup math is
//  0-safe, and stores are guarded by cnt).
// ---------------------------------------------------------------------------
__global__ __launch_bounds__(1024)
void sort_kernel(const int* __restrict__ start,
                 const int* __restrict__ end) {
    __shared__ int bins[NB2];            // 8 KB
    __shared__ int t0_off[TT + 1];
    __shared__ int aux[32];
    __shared__ int aux2[32];

    const int tid  = threadIdx.x;
    const int lane = tid & 31;
    const int wrp  = tid >> 5;

    for (int i = tid; i < NB2; i += 1024) bins[i] = 0;
    __syncthreads();

    // histogram over (t0, w-tier)
    for (int s = tid; s < SS; s += 1024) {
        const int t0 = start[s];
        const int w  = end[s] - t0 + 1;
        atomicAdd(&bins[t0 * 4 + ((w - 1) >> 3)], 1);
    }
    __syncthreads();

    // exclusive scan over 2048 bins (2 per thread + block scan)
    const int v0 = bins[2 * tid], v1 = bins[2 * tid + 1];
    const int run = v0 + v1;
    int inc = run;
#pragma unroll
    for (int off = 1; off < 32; off <<= 1) {
        const int t = __shfl_up_sync(0xffffffffu, inc, off);
        if (lane >= off) inc += t;
    }
    if (lane == 31) aux[wrp] = inc;
    __syncthreads();
    if (wrp == 0) {
        int a = aux[lane];
#pragma unroll
        for (int off = 1; off < 32; off <<= 1) {
            const int t = __shfl_up_sync(0xffffffffu, a, off);
            if (lane >= off) a += t;
        }
        aux[lane] = a;
    }
    __syncthreads();
    const int ex = inc - run + (wrp ? aux[wrp - 1] : 0);
    bins[2 * tid]     = ex;
    bins[2 * tid + 1] = ex + v0;
    __syncthreads();

    // snapshot per-t0 span offsets before scatter mutates bins
    if (tid < TT) t0_off[tid] = bins[tid * 4];
    if (tid == 0) t0_off[TT] = SS;
    __syncthreads();

    // scatter -> g_sorted (sorted by t0, then w-tier)
    for (int s = tid; s < SS; s += 1024) {
        const int t0 = start[s];
        const int w  = end[s] - t0 + 1;
        const int pos = atomicAdd(&bins[t0 * 4 + ((w - 1) >> 3)], 1);
        g_sorted[pos] = s;
    }
    __syncthreads();

    // scan per-t0 group counts (all 1024 threads; 0 past TT -> no divergence)
    int gc = 0;
    if (tid < TT) gc = (t0_off[tid + 1] - t0_off[tid] + GSZ - 1) >> 2;
    int gi = gc;
#pragma unroll
    for (int off = 1; off < 32; off <<= 1) {
        const int t = __shfl_up_sync(0xffffffffu, gi, off);
        if (lane >= off) gi += t;
    }
    if (lane == 31) aux2[wrp] = gi;
    __syncthreads();
    if (wrp == 0) {
        int a = aux2[lane];
#pragma unroll
        for (int off = 1; off < 32; off <<= 1) {
            const int t = __shfl_up_sync(0xffffffffu, a, off);
            if (lane >= off) a += t;
        }
        aux2[lane] = a;
    }
    __syncthreads();
    const int incl = gi + (wrp ? aux2[wrp - 1] : 0);
    const int g0   = incl - gc;

    if (tid < TT) {
        const int b0 = t0_off[tid];
        const int n  = t0_off[tid + 1] - b0;
        for (int k = 0, q = 0; k < n; k += GSZ, ++q) {
            const int cnt = min(GSZ, n - k);
            const int s0 = g_sorted[b0 + k];
            const int s1 = g_sorted[b0 + k + min(1, cnt - 1)];
            const int s2 = g_sorted[b0 + k + min(2, cnt - 1)];
            const int s3 = g_sorted[b0 + k + min(3, cnt - 1)];
            const int e0 = end[s0], e1 = end[s1], e2 = end[s2], e3 = end[s3];
            const int wmax = max(max(e0, e1), max(e2, e3)) - tid + 1;
            g_groups[g0 + q] = make_int4(s0 | (s1 << 16),
                                         s2 | (s3 << 16),
                                         tid | (wmax << 16),
                                         cnt);
        }
    }
    if (tid == 1023) g_ngroups = incl;
}

// ---------------------------------------------------------------------------
// Kernel 4: block per (group, batch). 256 threads cover E = 1024 floats.
// Prologue: ONE broadcast LDG.128 of the packed descriptor (all threads),
// then warps 0-3 stage the 4 members' probs coalesced + transposed into
// p4[32] (float4 per j). One __syncthreads.
// Hot loop: x4-unrolled with row clamp min(j+k, wmax-1); per step
// 4 LDG.128 + 4 LDS.128 + 64 FFMA -> MLP=4. Zero probs past each member's
// width (and past wmax) make clamped/padded rows contribute exactly 0.
// ---------------------------------------------------------------------------
__global__ __launch_bounds__(256)
void main_kernel(const float* __restrict__ x,
                 float* __restrict__ out) {
    const int gidx = blockIdx.x;
    if (gidx >= g_ngroups) return;
    const int b = blockIdx.y;

    __shared__ __align__(16) float p4f[32 * 4];

    const int tid  = threadIdx.x;
    const int lane = tid & 31;
    const int wrp  = tid >> 5;

    // one broadcast load of the packed descriptor
    const int4 gd = __ldg(&g_groups[gidx]);
    const int s0   = gd.x & 0xffff, s1 = gd.x >> 16;
    const int s2   = gd.y & 0xffff, s3 = gd.y >> 16;
    const int t0   = gd.z & 0xffff, wmax = gd.z >> 16;
    const int cnt  = gd.w;

    // warps 0-3 stage probs transposed: p4f[j*4 + g] = p[member g][j]
    if (wrp < 4) {
        const int sg = (wrp == 0) ? s0 : (wrp == 1) ? s1 : (wrp == 2) ? s2 : s3;
        const float v = __ldg(&g_probs[((size_t)b * SS + sg) * 32 + lane]);
        p4f[lane * 4 + wrp] = v;
    }
    __syncthreads();

    const float4* __restrict__ p4 = reinterpret_cast<const float4*>(p4f);
    const float4* __restrict__ xb =
        reinterpret_cast<const float4*>(x) + ((size_t)b * TT + t0) * 256 + tid;

    float4 a0 = make_float4(0.f,0.f,0.f,0.f);
    float4 a1 = make_float4(0.f,0.f,0.f,0.f);
    float4 a2 = make_float4(0.f,0.f,0.f,0.f);
    float4 a3 = make_float4(0.f,0.f,0.f,0.f);

    const int wm1 = wmax - 1;
#pragma unroll 1
    for (int j = 0; j < wmax; j += 4) {
        float4 v[4], q[4];
#pragma unroll
        for (int k = 0; k < 4; ++k) {
            const int r = min(j + k, wm1);      // clamped; padded rows get q=0
            v[k] = xb[(size_t)r * 256];
            q[k] = p4[j + k];                   // j+k <= 31 (wmax <= 30)
        }
#pragma unroll
        for (int k = 0; k < 4; ++k) {
            a0.x += q[k].x * v[k].x; a0.y += q[k].x * v[k].y;
            a0.z += q[k].x * v[k].z; a0.w += q[k].x * v[k].w;
            a1.x += q[k].y * v[k].x; a1.y += q[k].y * v[k].y;
            a1.z += q[k].y * v[k].z; a1.w += q[k].y * v[k].w;
            a2.x += q[k].z * v[k].x; a2.y += q[k].z * v[k].y;
            a2.z += q[k].z * v[k].z; a2.w += q[k].z * v[k].w;
            a3.x += q[k].w * v[k].x; a3.y += q[k].w * v[k].y;
            a3.z += q[k].w * v[k].z; a3.w += q[k].w * v[k].w;
        }
    }

    float4* __restrict__ o4 =
        reinterpret_cast<float4*>(out) + (size_t)b * SS * 256 + tid;
    o4[(size_t)s0 * 256] = a0;
    if (cnt > 1) o4[(size_t)s1 * 256] = a1;
    if (cnt > 2) o4[(size_t)s2 * 256] = a2;
    if (cnt > 3) o4[(size_t)s3 * 256] = a3;
}

// ---------------------------------------------------------------------------
// Launch
// Inputs (metadata order): x (B,T,E) f32, W (E,1) f32, b (1,) f32,
//                          start (S,) i32, end (S,) i32
// Output: (B, S, E) f32
// ---------------------------------------------------------------------------
extern "C" void kernel_launch(void* const* d_in, const int* in_sizes, int n_in,
                              void* d_out, int out_size) {
    const float* x     = (const float*)d_in[0];
    const float* W     = (const float*)d_in[1];
    const float* bias  = (const float*)d_in[2];
    const int*   start = (const int*)d_in[3];
    const int*   end   = (const int*)d_in[4];
    float*       out   = (float*)d_out;

    score_kernel<<<(BB * TT) / 8, 256>>>(x, W, bias);
    prob_kernel<<<(BB * SS) / 8, 256>>>(start, end);
    sort_kernel<<<1, 1024>>>(start, end);

    dim3 grid(NGROUPS_MAX, BB);
    main_kernel<<<grid, 256>>>(x, out);
}

// round 16
// speedup vs baseline: 1.2047x; 1.2047x over previous
#include <cuda_runtime.h>
#include <math_constants.h>

// Problem constants (fixed by the reference)
#define BB 2
#define TT 512
#define EE 1024
#define SS 2048
#define AA 30

#define NB2 (TT * 4)            // sort key: t0*4 + (w-1)/8
#define NPAIRS_MAX 1280         // sum ceil(n_t/2) <= (2048 + 512)/2

__device__ float g_scores[BB * TT];
__device__ int   g_sorted[SS];
__device__ int2  g_pairs[NPAIRS_MAX];   // x = s0|s1<<16, y = t0|cnt<<16
__device__ int   g_npairs;

// ---------------------------------------------------------------------------
// Prep kernel (fused): blocks 0..31 compute scores (warp-per-row, 32 warps
// each); block 32 runs the counting sort (by t0, w-tier) and emits span PAIRS
// sharing the same t0 (w-tier sorted -> tight pair wmax).
// ---------------------------------------------------------------------------
__global__ __launch_bounds__(1024)
void prep_kernel(const float* __restrict__ x,
                 const float* __restrict__ W,
                 const float* __restrict__ bias,
                 const int* __restrict__ start,
                 const int* __restrict__ end) {
    __shared__ int bins[NB2];            // 8 KB (sort block only)
    __shared__ int t0_off[TT + 1];
    __shared__ int aux[32];
    __shared__ int aux2[32];

    const int tid  = threadIdx.x;
    const int lane = tid & 31;
    const int wrp  = tid >> 5;

    if (blockIdx.x < 32) {
        // ---------------- score part: 32 blocks x 32 warps = 1024 rows ------
        const int row = blockIdx.x * 32 + wrp;
        const float4* __restrict__ xr =
            reinterpret_cast<const float4*>(x) + (size_t)row * 256;
        const float4* __restrict__ w4 = reinterpret_cast<const float4*>(W);

        float acc = 0.0f;
#pragma unroll
        for (int i = 0; i < 8; ++i) {
            const float4 xv = xr[lane + i * 32];
            const float4 wv = w4[lane + i * 32];
            acc += xv.x * wv.x + xv.y * wv.y + xv.z * wv.z + xv.w * wv.w;
        }
#pragma unroll
        for (int off = 16; off; off >>= 1)
            acc += __shfl_xor_sync(0xffffffffu, acc, off);

        if (lane == 0)
            g_scores[row] = fmaxf(acc + bias[0], 0.0f);
        return;
    }

    // ---------------- sort part: single block (blockIdx.x == 32) -----------
    for (int i = tid; i < NB2; i += 1024) bins[i] = 0;
    __syncthreads();

    // histogram over (t0, w-tier)
    for (int s = tid; s < SS; s += 1024) {
        const int t0 = start[s];
        const int w  = end[s] - t0 + 1;
        atomicAdd(&bins[t0 * 4 + ((w - 1) >> 3)], 1);
    }
    __syncthreads();

    // exclusive scan over 2048 bins (2 per thread + block scan)
    const int v0 = bins[2 * tid], v1 = bins[2 * tid + 1];
    const int run = v0 + v1;
    int inc = run;
#pragma unroll
    for (int off = 1; off < 32; off <<= 1) {
        const int t = __shfl_up_sync(0xffffffffu, inc, off);
        if (lane >= off) inc += t;
    }
    if (lane == 31) aux[wrp] = inc;
    __syncthreads();
    if (wrp == 0) {
        int a = aux[lane];
#pragma unroll
        for (int off = 1; off < 32; off <<= 1) {
            const int t = __shfl_up_sync(0xffffffffu, a, off);
            if (lane >= off) a += t;
        }
        aux[lane] = a;
    }
    __syncthreads();
    const int ex = inc - run + (wrp ? aux[wrp - 1] : 0);
    bins[2 * tid]     = ex;
    bins[2 * tid + 1] = ex + v0;
    __syncthreads();

    // snapshot per-t0 span offsets before scatter mutates bins
    if (tid < TT) t0_off[tid] = bins[tid * 4];
    if (tid == 0) t0_off[TT] = SS;
    __syncthreads();

    // scatter -> g_sorted (sorted by t0, then w-tier)
    for (int s = tid; s < SS; s += 1024) {
        const int t0 = start[s];
        const int w  = end[s] - t0 + 1;
        const int pos = atomicAdd(&bins[t0 * 4 + ((w - 1) >> 3)], 1);
        g_sorted[pos] = s;
    }
    __syncthreads();

    // scan per-t0 PAIR counts (all 1024 threads; 0 past TT)
    int gc = 0;
    if (tid < TT) gc = (t0_off[tid + 1] - t0_off[tid] + 1) >> 1;
    int gi = gc;
#pragma unroll
    for (int off = 1; off < 32; off <<= 1) {
        const int t = __shfl_up_sync(0xffffffffu, gi, off);
        if (lane >= off) gi += t;
    }
    if (lane == 31) aux2[wrp] = gi;
    __syncthreads();
    if (wrp == 0) {
        int a = aux2[lane];
#pragma unroll
        for (int off = 1; off < 32; off <<= 1) {
            const int t = __shfl_up_sync(0xffffffffu, a, off);
            if (lane >= off) a += t;
        }
        aux2[lane] = a;
    }
    __syncthreads();
    const int incl = gi + (wrp ? aux2[wrp - 1] : 0);
    const int g0   = incl - gc;

    if (tid < TT) {
        const int b0 = t0_off[tid];
        const int n  = t0_off[tid + 1] - b0;
        for (int k = 0, q = 0; k < n; k += 2, ++q) {
            const int cnt = min(2, n - k);
            const int s0 = g_sorted[b0 + k];
            const int s1 = g_sorted[b0 + k + cnt - 1];   // dup for cnt==1
            g_pairs[g0 + q] = make_int2(s0 | (s1 << 16), tid | (cnt << 16));
        }
    }
    if (tid == 1023) g_npairs = incl;
}

// ---------------------------------------------------------------------------
// Main kernel: block per (pair, batch). 256 threads cover E = 1024 floats.
// Prologue: one broadcast LDG.64 of the pair descriptor; warps 0/1 compute
// the inline softmax for member 0/1 from g_scores (p = 0 past each width)
// and stage interleaved probs p2[j] = (pA_j, pB_j) in smem. One sync.
// Hot loop: x4-unrolled, row clamp min(j+k, wmax-1) -> MLP=4;
// per j: 1 LDG.128 + 1 LDS.64 + 8 FFMA, serving 2 spans per row read.
// ---------------------------------------------------------------------------
__global__ __launch_bounds__(256)
void main_kernel(const float* __restrict__ x,
                 const int* __restrict__ end,
                 float* __restrict__ out) {
    const int gidx = blockIdx.x;
    if (gidx >= g_npairs) return;
    const int b = blockIdx.y;

    __shared__ __align__(8) float p2f[64];
    __shared__ int shw[2];

    const int tid  = threadIdx.x;
    const int lane = tid & 31;
    const int wrp  = tid >> 5;

    const int2 pd = __ldg(&g_pairs[gidx]);
    const int s0  = pd.x & 0xffff, s1 = pd.x >> 16;
    const int t0  = pd.y & 0xffff, cnt = pd.y >> 16;

    if (wrp < 2) {
        const int sg = wrp ? s1 : s0;
        const int w  = __ldg(&end[sg]) - t0 + 1;           // 1..30
        float sc = (lane < w) ? g_scores[b * TT + t0 + lane] : -CUDART_INF_F;
        float m = sc;
#pragma unroll
        for (int off = 16; off; off >>= 1)
            m = fmaxf(m, __shfl_xor_sync(0xffffffffu, m, off));
        const float e = (lane < w) ? __expf(sc - m) : 0.0f;
        float sum = e;
#pragma unroll
        for (int off = 16; off; off >>= 1)
            sum += __shfl_xor_sync(0xffffffffu, sum, off);
        p2f[lane * 2 + wrp] = e / sum;                     // exactly 0 past w
        if (lane == 0) shw[wrp] = w;
    }
    __syncthreads();

    const int wmax = max(shw[0], shw[1]);
    const int wm1  = wmax - 1;

    const float2* __restrict__ p2 = reinterpret_cast<const float2*>(p2f);
    const float4* __restrict__ xb =
        reinterpret_cast<const float4*>(x) + ((size_t)b * TT + t0) * 256 + tid;

    float4 a0 = make_float4(0.f, 0.f, 0.f, 0.f);
    float4 a1 = make_float4(0.f, 0.f, 0.f, 0.f);

#pragma unroll 1
    for (int j = 0; j < wmax; j += 4) {
        float4 v[4];
        float2 q[4];
#pragma unroll
        for (int k = 0; k < 4; ++k) {
            const int r = min(j + k, wm1);      // clamped; padded rows get q=0
            v[k] = xb[(size_t)r * 256];
            q[k] = p2[j + k];                   // j+k <= 31 (wmax <= 30)
        }
#pragma unroll
        for (int k = 0; k < 4; ++k) {
            a0.x += q[k].x * v[k].x; a0.y += q[k].x * v[k].y;
            a0.z += q[k].x * v[k].z; a0.w += q[k].x * v[k].w;
            a1.x += q[k].y * v[k].x; a1.y += q[k].y * v[k].y;
            a1.z += q[k].y * v[k].z; a1.w += q[k].y * v[k].w;
        }
    }

    float4* __restrict__ o4 =
        reinterpret_cast<float4*>(out) + (size_t)b * SS * 256 + tid;
    o4[(size_t)s0 * 256] = a0;
    if (cnt > 1) o4[(size_t)s1 * 256] = a1;
}

// ---------------------------------------------------------------------------
// Launch
// Inputs (metadata order): x (B,T,E) f32, W (E,1) f32, b (1,) f32,
//                          start (S,) i32, end (S,) i32
// Output: (B, S, E) f32
// ---------------------------------------------------------------------------
extern "C" void kernel_launch(void* const* d_in, const int* in_sizes, int n_in,
                              void* d_out, int out_size) {
    const float* x     = (const float*)d_in[0];
    const float* W     = (const float*)d_in[1];
    const float* bias  = (const float*)d_in[2];
    const int*   start = (const int*)d_in[3];
    const int*   end   = (const int*)d_in[4];
    float*       out   = (float*)d_out;

    // Fused prep: blocks 0..31 = scores, block 32 = sort + pair building
    prep_kernel<<<33, 1024>>>(x, W, bias, start, end);

    // Main: block per (pair, batch)
    dim3 grid(NPAIRS_MAX, BB);
    main_kernel<<<grid, 256>>>(x, end, out);
}